// round 9
// baseline (speedup 1.0000x reference)
#include <cuda_runtime.h>
#include <cstdint>

// Problem constants
#define B_ROWS   65536
#define N_SPARSE 26
#define VOCAB    5000
#define N_DENSE  13

#define THREADS    512
#define ROWS_PB    224        // 2 subs/row -> 448 worker threads of 512
#define NBLOCKS    293        // ceil(65536/224); ~2 blocks per SM
#define CHUNK_ROWS 56
#define N_CHUNKS   4

#define N_CACHED 18           // features [0,18) via smem; [18,26) + crosses direct
#define PASS_NF  2
#define N_PASSES 9

// Dynamic smem layout (bytes), all 16B-aligned
#define BUF_BYTES   (PASS_NF * VOCAB * 4)       // 40000
#define IDX_OFF     (2 * BUF_BYTES)             // 80000
#define IDX_BYTES   (ROWS_PB * N_SPARSE * 4)    // 23296
#define DENSE_OFF   (IDX_OFF + IDX_BYTES)       // 103296
#define DENSE_BYTES (ROWS_PB * N_DENSE * 4)     // 11648
#define MBAR_OFF    (DENSE_OFF + DENSE_BYTES)   // 114944
#define SMEM_TOTAL  (MBAR_OFF + 6 * 8)          // 114992  -> 2 blocks/SM

__device__ __forceinline__ uint32_t smem_u32(const void* p) {
    return (uint32_t)__cvta_generic_to_shared(p);
}
__device__ __forceinline__ void mbar_init(uint32_t mbar, uint32_t count) {
    asm volatile("mbarrier.init.shared.b64 [%0], %1;" :: "r"(mbar), "r"(count) : "memory");
}
__device__ __forceinline__ void mbar_expect_tx(uint32_t mbar, uint32_t bytes) {
    asm volatile("mbarrier.arrive.expect_tx.shared.b64 _, [%0], %1;"
                 :: "r"(mbar), "r"(bytes) : "memory");
}
__device__ __forceinline__ void mbar_wait(uint32_t mbar, uint32_t parity) {
    uint32_t done = 0;
    while (!done) {
        asm volatile(
            "{\n\t.reg .pred p;\n\t"
            "mbarrier.try_wait.parity.acquire.cta.shared::cta.b64 p, [%1], %2, 0x989680;\n\t"
            "selp.b32 %0, 1, 0, p;\n\t}"
            : "=r"(done) : "r"(mbar), "r"(parity) : "memory");
    }
}
__device__ __forceinline__ void bulk_g2s(uint32_t dst, const void* src,
                                         uint32_t bytes, uint32_t mbar) {
    asm volatile(
        "cp.async.bulk.shared::cta.global.mbarrier::complete_tx::bytes [%0], [%1], %2, [%3];"
        :: "r"(dst), "l"(src), "r"(bytes), "r"(mbar) : "memory");
}

__global__ __launch_bounds__(THREADS, 2) void wide_kernel(
    const float* __restrict__ dense,        // [B, 13]
    const float* __restrict__ emb_table,    // [26, 5000]
    const float* __restrict__ cross_table0, // [25e6]
    const float* __restrict__ cross_table1, // [25e6]
    const float* __restrict__ dense_w,      // [13]
    const int*   __restrict__ sparse_idx,   // [B, 26] int32
    float*       __restrict__ out)          // [B]
{
    extern __shared__ __align__(16) char smem[];
    float* s_buf[2] = { (float*)smem, (float*)(smem + BUF_BYTES) };
    int*   s_idx    = (int*)(smem + IDX_OFF);
    float* s_dense  = (float*)(smem + DENSE_OFF);

    const uint32_t mb_io0 = smem_u32(smem + MBAR_OFF);        // 4 io chunk barriers
    const uint32_t mb_b0  = smem_u32(smem + MBAR_OFF + 32);   // 2 slice barriers
    const uint32_t buf_s[2] = { smem_u32(smem), smem_u32(smem + BUF_BYTES) };

    const int tid  = threadIdx.x;
    const int row0 = blockIdx.x * ROWS_PB;
    const int rows = min(ROWS_PB, B_ROWS - row0);

    if (tid == 0) {
        #pragma unroll
        for (int c = 0; c < N_CHUNKS; c++) mbar_init(mb_io0 + 8 * c, 1);
        mbar_init(mb_b0, 1);
        mbar_init(mb_b0 + 8, 1);
    }
    __syncthreads();

    // Issue all initial async copies: 4 io chunks (idx+dense) + 2 table slices.
    if (tid == 0) {
        #pragma unroll
        for (int c = 0; c < N_CHUNKS; c++) {
            const int crow0 = c * CHUNK_ROWS;
            const int crows = max(0, min(CHUNK_ROWS, rows - crow0));
            const uint32_t ib = (uint32_t)crows * N_SPARSE * 4;
            const uint32_t db = (uint32_t)crows * N_DENSE * 4;
            mbar_expect_tx(mb_io0 + 8 * c, ib + db);   // 0 bytes -> flips immediately
            if (crows > 0) {
                bulk_g2s(smem_u32(s_idx + crow0 * N_SPARSE),
                         sparse_idx + (size_t)(row0 + crow0) * N_SPARSE, ib, mb_io0 + 8 * c);
                bulk_g2s(smem_u32(s_dense + crow0 * N_DENSE),
                         dense + (size_t)(row0 + crow0) * N_DENSE, db, mb_io0 + 8 * c);
            }
        }
        mbar_expect_tx(mb_b0, BUF_BYTES);
        bulk_g2s(buf_s[0], emb_table + 0 * PASS_NF * VOCAB, BUF_BYTES, mb_b0);
        mbar_expect_tx(mb_b0 + 8, BUF_BYTES);
        bulk_g2s(buf_s[1], emb_table + 1 * PASS_NF * VOCAB, BUF_BYTES, mb_b0 + 8);
    }

    const int  sub    = tid & 1;             // 2 sub-threads per row (round-7 split)
    const int  rawrow = tid >> 1;
    const bool active = (rawrow < rows);

    // Wait only for this thread's own io chunk.
    const int chunk = min(rawrow / CHUNK_ROWS, N_CHUNKS - 1);
    mbar_wait(mb_io0 + 8 * chunk, 0);

    const int* my = &s_idx[rawrow * N_SPARSE];
    float acc = 0.0f;

    if (active) {
        if (sub == 0) {
            acc += __ldg(&cross_table0[my[0] * VOCAB + my[1]]);     // DRAM first
            #pragma unroll
            for (int f = N_CACHED; f < 22; f++)                     // 18..21
                acc += __ldg(&emb_table[f * VOCAB + my[f]]);
        } else {
            acc += __ldg(&cross_table1[my[2] * VOCAB + my[3]]);
            #pragma unroll
            for (int f = 22; f < N_SPARSE; f++)                     // 22..25
                acc += __ldg(&emb_table[f * VOCAB + my[f]]);
        }

        // Dense dot, pair-split (7 / 6)
        const float* dr = &s_dense[rawrow * N_DENSE];
        if (sub == 0) {
            #pragma unroll
            for (int d = 0; d < 7; d++) acc += dr[d] * __ldg(&dense_w[d]);
        } else {
            #pragma unroll
            for (int d = 7; d < N_DENSE; d++) acc += dr[d] * __ldg(&dense_w[d]);
        }
    }

    // Double-buffered cached passes: 9 passes x 2 features over [0, 18).
    // Each sub takes one feature per pass (9 cached loads per sub).
    #pragma unroll
    for (int p = 0; p < N_PASSES; p++) {
        const int b = p & 1;
        mbar_wait(mb_b0 + 8 * b, (p >> 1) & 1);

        if (active) {
            const float* tb = s_buf[b];
            const int f0 = p * PASS_NF;
            acc += tb[sub * VOCAB + my[f0 + sub]];
        }

        __syncthreads();   // all consumers done with buffer b

        if (p + 2 < N_PASSES && tid == 0) {
            mbar_expect_tx(mb_b0 + 8 * b, BUF_BYTES);
            bulk_g2s(buf_s[b], emb_table + (p + 2) * PASS_NF * VOCAB, BUF_BYTES, mb_b0 + 8 * b);
        }
    }

    // Pair combine + store
    acc += __shfl_xor_sync(0xFFFFFFFFu, acc, 1);
    if (active && sub == 0) out[row0 + rawrow] = acc;
}

extern "C" void kernel_launch(void* const* d_in, const int* in_sizes, int n_in,
                              void* d_out, int out_size)
{
    const float* dense        = nullptr;
    const float* emb_table    = nullptr;
    const float* cross_table0 = nullptr;
    const float* cross_table1 = nullptr;
    const float* dense_w      = nullptr;
    const int*   sparse_idx   = nullptr;

    for (int i = 0; i < n_in; i++) {
        const long long sz = in_sizes[i];
        if      (sz == (long long)B_ROWS * N_DENSE)   dense      = (const float*)d_in[i];
        else if (sz == (long long)N_SPARSE * VOCAB)   emb_table  = (const float*)d_in[i];
        else if (sz == (long long)VOCAB * VOCAB) {
            if (!cross_table0) cross_table0 = (const float*)d_in[i];
            else               cross_table1 = (const float*)d_in[i];
        }
        else if (sz == N_DENSE)                       dense_w    = (const float*)d_in[i];
        else if (sz == (long long)B_ROWS * N_SPARSE)  sparse_idx = (const int*)d_in[i];
    }

    float* out = (float*)d_out;

    static bool attr_set = false;
    if (!attr_set) {
        cudaFuncSetAttribute(wide_kernel,
                             cudaFuncAttributeMaxDynamicSharedMemorySize, SMEM_TOTAL);
        attr_set = true;
    }

    wide_kernel<<<NBLOCKS, THREADS, SMEM_TOTAL>>>(dense, emb_table,
                                                  cross_table0, cross_table1,
                                                  dense_w, sparse_idx, out);
}

// round 10
// speedup vs baseline: 1.3810x; 1.3810x over previous
#include <cuda_runtime.h>
#include <cstdint>

// Problem constants
#define B_ROWS   65536
#define N_SPARSE 26
#define VOCAB    5000
#define N_DENSE  13

#define THREADS    1024
#define ROWS_PB    448        // one direct thread + one cached thread per row
#define NBLOCKS    147        // 146*448=65408, last block 128 rows
#define CHUNK_ROWS 112
#define N_CHUNKS   4

#define N_CACHED 18           // features [0,18) via smem; [18,26) + crosses direct
#define PASS_NF  3
#define N_PASSES 6

// Dynamic smem layout (bytes), 16B-aligned
#define BUF_BYTES   (PASS_NF * VOCAB * 4)       // 60000
#define IDX_OFF     (2 * BUF_BYTES)             // 120000
#define IDX_BYTES   (ROWS_PB * N_SPARSE * 4)    // 46592
#define DENSE_OFF   (IDX_OFF + IDX_BYTES)       // 166592
#define DENSE_BYTES (ROWS_PB * N_DENSE * 4)     // 23296
#define PARTD_OFF   (DENSE_OFF + DENSE_BYTES)   // 189888
#define PARTC_OFF   (PARTD_OFF + ROWS_PB * 4)   // 191680
#define MBAR_OFF    (PARTC_OFF + ROWS_PB * 4)   // 193472
#define SMEM_TOTAL  (MBAR_OFF + 6 * 8)          // 193520

__device__ __forceinline__ uint32_t smem_u32(const void* p) {
    return (uint32_t)__cvta_generic_to_shared(p);
}
__device__ __forceinline__ void mbar_init(uint32_t mbar, uint32_t count) {
    asm volatile("mbarrier.init.shared.b64 [%0], %1;" :: "r"(mbar), "r"(count) : "memory");
}
__device__ __forceinline__ void mbar_expect_tx(uint32_t mbar, uint32_t bytes) {
    asm volatile("mbarrier.arrive.expect_tx.shared.b64 _, [%0], %1;"
                 :: "r"(mbar), "r"(bytes) : "memory");
}
__device__ __forceinline__ void mbar_wait(uint32_t mbar, uint32_t parity) {
    uint32_t done = 0;
    while (!done) {
        asm volatile(
            "{\n\t.reg .pred p;\n\t"
            "mbarrier.try_wait.parity.acquire.cta.shared::cta.b64 p, [%1], %2, 0x989680;\n\t"
            "selp.b32 %0, 1, 0, p;\n\t}"
            : "=r"(done) : "r"(mbar), "r"(parity) : "memory");
    }
}
__device__ __forceinline__ void bulk_g2s(uint32_t dst, const void* src,
                                         uint32_t bytes, uint32_t mbar) {
    asm volatile(
        "cp.async.bulk.shared::cta.global.mbarrier::complete_tx::bytes [%0], [%1], %2, [%3];"
        :: "r"(dst), "l"(src), "r"(bytes), "r"(mbar) : "memory");
}

__global__ __launch_bounds__(THREADS, 1) void wide_kernel(
    const float* __restrict__ dense,        // [B, 13]
    const float* __restrict__ emb_table,    // [26, 5000]
    const float* __restrict__ cross_table0, // [25e6]
    const float* __restrict__ cross_table1, // [25e6]
    const float* __restrict__ dense_w,      // [13]
    const int*   __restrict__ sparse_idx,   // [B, 26] int32
    float*       __restrict__ out)          // [B]
{
    extern __shared__ __align__(16) char smem[];
    float* s_buf[2]  = { (float*)smem, (float*)(smem + BUF_BYTES) };
    int*   s_idx     = (int*)(smem + IDX_OFF);
    float* s_dense   = (float*)(smem + DENSE_OFF);
    float* s_part_d  = (float*)(smem + PARTD_OFF);
    float* s_part_c  = (float*)(smem + PARTC_OFF);

    const uint32_t mb_io0 = smem_u32(smem + MBAR_OFF);        // 4 io chunk barriers
    const uint32_t mb_b0  = smem_u32(smem + MBAR_OFF + 32);   // 2 slice barriers
    const uint32_t buf_s[2] = { smem_u32(smem), smem_u32(smem + BUF_BYTES) };

    const int tid  = threadIdx.x;
    const int row0 = blockIdx.x * ROWS_PB;
    const int rows = min(ROWS_PB, B_ROWS - row0);

    if (tid == 0) {
        #pragma unroll
        for (int c = 0; c < N_CHUNKS; c++) mbar_init(mb_io0 + 8 * c, 1);
        mbar_init(mb_b0, 1);
        mbar_init(mb_b0 + 8, 1);
    }
    __syncthreads();

    // Issue all initial async copies: 4 io chunks (idx+dense) + 2 table slices.
    if (tid == 0) {
        #pragma unroll
        for (int c = 0; c < N_CHUNKS; c++) {
            const int crow0 = c * CHUNK_ROWS;
            const int crows = max(0, min(CHUNK_ROWS, rows - crow0));
            const uint32_t ib = (uint32_t)crows * N_SPARSE * 4;
            const uint32_t db = (uint32_t)crows * N_DENSE * 4;
            mbar_expect_tx(mb_io0 + 8 * c, ib + db);   // 0 bytes -> flips immediately
            if (crows > 0) {
                bulk_g2s(smem_u32(s_idx + crow0 * N_SPARSE),
                         sparse_idx + (size_t)(row0 + crow0) * N_SPARSE, ib, mb_io0 + 8 * c);
                bulk_g2s(smem_u32(s_dense + crow0 * N_DENSE),
                         dense + (size_t)(row0 + crow0) * N_DENSE, db, mb_io0 + 8 * c);
            }
        }
        mbar_expect_tx(mb_b0, BUF_BYTES);
        bulk_g2s(buf_s[0], emb_table + 0 * PASS_NF * VOCAB, BUF_BYTES, mb_b0);
        mbar_expect_tx(mb_b0 + 8, BUF_BYTES);
        bulk_g2s(buf_s[1], emb_table + 1 * PASS_NF * VOCAB, BUF_BYTES, mb_b0 + 8);
    }

    if (tid < 512) {
        // ---------------- DIRECT HALF: one thread per row ----------------
        const int r = tid;
        if (r < rows) {
            const int chunk = min(r / CHUNK_ROWS, N_CHUNKS - 1);
            mbar_wait(mb_io0 + 8 * chunk, 0);

            const int* my = &s_idx[r * N_SPARSE];
            float a = 0.0f;
            // Two DRAM cross gathers first (longest latency)
            a += __ldg(&cross_table0[my[0] * VOCAB + my[1]]);
            a += __ldg(&cross_table1[my[2] * VOCAB + my[3]]);
            // 8 direct emb features (L2-hot)
            #pragma unroll
            for (int f = N_CACHED; f < N_SPARSE; f++)
                a += __ldg(&emb_table[f * VOCAB + my[f]]);
            // Dense dot
            const float* dr = &s_dense[r * N_DENSE];
            #pragma unroll
            for (int d = 0; d < N_DENSE; d++)
                a += dr[d] * __ldg(&dense_w[d]);

            s_part_d[r] = a;
        }
    } else {
        // ---------------- CACHED HALF: one thread per row ----------------
        const int r = tid - 512;
        if (r < rows) {
            const int chunk = min(r / CHUNK_ROWS, N_CHUNKS - 1);
            mbar_wait(mb_io0 + 8 * chunk, 0);
        }
        const int* my = &s_idx[r * N_SPARSE];   // only read when r < rows

        float a = 0.0f;
        #pragma unroll
        for (int p = 0; p < N_PASSES; p++) {
            const int b = p & 1;
            mbar_wait(mb_b0 + 8 * b, (p >> 1) & 1);

            if (r < rows) {
                const float* tb = s_buf[b];
                const int f0 = p * PASS_NF;
                a += tb[0 * VOCAB + my[f0 + 0]];
                a += tb[1 * VOCAB + my[f0 + 1]];
                a += tb[2 * VOCAB + my[f0 + 2]];
            }

            // Barrier over the cached half only (warps 16..31): buffer b free.
            asm volatile("bar.sync 1, 512;" ::: "memory");

            if (p + 2 < N_PASSES && tid == 512) {
                mbar_expect_tx(mb_b0 + 8 * b, BUF_BYTES);
                bulk_g2s(buf_s[b], emb_table + (p + 2) * PASS_NF * VOCAB,
                         BUF_BYTES, mb_b0 + 8 * b);
            }
        }
        if (r < rows) s_part_c[r] = a;
    }

    __syncthreads();

    // Combine halves and store (threads 0..rows-1)
    if (tid < rows) out[row0 + tid] = s_part_d[tid] + s_part_c[tid];
}

extern "C" void kernel_launch(void* const* d_in, const int* in_sizes, int n_in,
                              void* d_out, int out_size)
{
    const float* dense        = nullptr;
    const float* emb_table    = nullptr;
    const float* cross_table0 = nullptr;
    const float* cross_table1 = nullptr;
    const float* dense_w      = nullptr;
    const int*   sparse_idx   = nullptr;

    for (int i = 0; i < n_in; i++) {
        const long long sz = in_sizes[i];
        if      (sz == (long long)B_ROWS * N_DENSE)   dense      = (const float*)d_in[i];
        else if (sz == (long long)N_SPARSE * VOCAB)   emb_table  = (const float*)d_in[i];
        else if (sz == (long long)VOCAB * VOCAB) {
            if (!cross_table0) cross_table0 = (const float*)d_in[i];
            else               cross_table1 = (const float*)d_in[i];
        }
        else if (sz == N_DENSE)                       dense_w    = (const float*)d_in[i];
        else if (sz == (long long)B_ROWS * N_SPARSE)  sparse_idx = (const int*)d_in[i];
    }

    float* out = (float*)d_out;

    static bool attr_set = false;
    if (!attr_set) {
        cudaFuncSetAttribute(wide_kernel,
                             cudaFuncAttributeMaxDynamicSharedMemorySize, SMEM_TOTAL);
        attr_set = true;
    }

    wide_kernel<<<NBLOCKS, THREADS, SMEM_TOTAL>>>(dense, emb_table,
                                                  cross_table0, cross_table1,
                                                  dense_w, sparse_idx, out);
}